// round 1
// baseline (speedup 1.0000x reference)
#include <cuda_runtime.h>
#include <math.h>

#define NN 50000
#define EE 800000
#define HH 128
#define EDIM 32
#define GG 64
#define AA 16
#define BN_EPS 1e-5f

// ---------------- scratch (static device globals; no allocation) ----------------
__device__ float g_y[(size_t)NN * HH];   // x + agg (GEMM input)
__device__ float g_u[(size_t)NN * HH];   // GEMM output (pre-BN)
__device__ float g_h[(size_t)NN * HH];   // layer output
__device__ float g_sum[HH];
__device__ float g_sumsq[HH];
__device__ float g_scale[HH];
__device__ float g_shift[HH];
__device__ float g_pooled[GG * HH];
__device__ int   g_idx64;                // 1 if edge_index/batch are int64

// ---------------- int32/int64 index handling ----------------
__device__ __forceinline__ long long read_idx(const void* p, long long i, bool i64) {
    if (i64) return ((const long long*)p)[i];
    return (long long)((const int*)p)[i];
}

// Detect int64 vs int32: for int64 (values < 2^31, nonneg), every odd 32-bit word
// is zero. For random int32 indices in [0,50000), 4096 consecutive odd words being
// all zero is impossible.
__global__ void detect_kernel(const unsigned int* __restrict__ w) {
    __shared__ int f;
    if (threadIdx.x == 0) f = 0;
    __syncthreads();
    int local = 0;
    for (int i = threadIdx.x * 2 + 1; i < 8192; i += 512)
        if (w[i]) local = 1;
    if (local) atomicOr(&f, 1);
    __syncthreads();
    if (threadIdx.x == 0) g_idx64 = f ? 0 : 1;
}

// ---------------- y = src (copy), zero BN stats ----------------
__global__ void copy_init_kernel(const float4* __restrict__ src, int n4) {
    if (blockIdx.x == 0 && threadIdx.x < HH) {
        g_sum[threadIdx.x] = 0.f;
        g_sumsq[threadIdx.x] = 0.f;
    }
    int i = blockIdx.x * blockDim.x + threadIdx.x;
    if (i < n4) ((float4*)g_y)[i] = src[i];
}

// ---------------- edge kernel ----------------
// msg = relu(x[src] + edge_attr @ We.T + be); red-add into g_y[dst]
// 1 warp handles 8 edges; channel mapping c = 4*lane + j (float4 everywhere).
__global__ void __launch_bounds__(256) edge_kernel(
    const float* __restrict__ xin_ext, int use_h,
    const float* __restrict__ ea,
    const void* __restrict__ eiv,
    const float* __restrict__ We,   // [128][32] row-major
    const float* __restrict__ be)
{
    __shared__ float we_s[EDIM * HH];   // we_s[k*128 + c] = We[c][k]
    const int tid = threadIdx.x;
    for (int idx = tid; idx < EDIM * HH; idx += 256) {
        int k = idx >> 7, c = idx & 127;
        we_s[idx] = We[c * EDIM + k];
    }

    const float* __restrict__ xin = use_h ? g_h : xin_ext;
    const int lane = tid & 31, warp = tid >> 5;
    const int e0 = (blockIdx.x * 8 + warp) * 8;
    const bool i64 = (g_idx64 != 0);

    int sreg = 0, dreg = 0;
    if (lane < 8) {
        long long e = e0 + lane;
        sreg = (int)read_idx(eiv, e, i64);
        dreg = (int)read_idx(eiv, (long long)EE + e, i64);
    }

    float a[8];
#pragma unroll
    for (int e = 0; e < 8; e++)
        a[e] = ea[(size_t)(e0 + e) * EDIM + lane];

    const float4 bev = *(const float4*)(be + 4 * lane);
    float4 acc[8];
#pragma unroll
    for (int e = 0; e < 8; e++) acc[e] = bev;

    __syncthreads();

#pragma unroll 4
    for (int k = 0; k < EDIM; k++) {
        float4 w = *(const float4*)(we_s + k * HH + 4 * lane);
#pragma unroll
        for (int e = 0; e < 8; e++) {
            float ae = __shfl_sync(0xffffffffu, a[e], k);
            acc[e].x += w.x * ae;
            acc[e].y += w.y * ae;
            acc[e].z += w.z * ae;
            acc[e].w += w.w * ae;
        }
    }

#pragma unroll
    for (int e = 0; e < 8; e++) {
        int s = __shfl_sync(0xffffffffu, sreg, e);
        int d = __shfl_sync(0xffffffffu, dreg, e);
        const float4 xv = *(const float4*)(xin + (size_t)s * HH + 4 * lane);
        float mx = fmaxf(acc[e].x + xv.x, 0.f);
        float my = fmaxf(acc[e].y + xv.y, 0.f);
        float mz = fmaxf(acc[e].z + xv.z, 0.f);
        float mw = fmaxf(acc[e].w + xv.w, 0.f);
        float* p = g_y + (size_t)d * HH + 4 * lane;
        asm volatile("red.global.add.v4.f32 [%0], {%1,%2,%3,%4};"
                     :: "l"(p), "f"(mx), "f"(my), "f"(mz), "f"(mw) : "memory");
    }
}

// ---------------- node GEMM: u = g_y @ W.T + b ----------------
// Block tile: 64 rows x 128 cols. Thread (tr,tc): 4 rows x 8 cols.
__global__ void __launch_bounds__(256) node_gemm_kernel(
    const float* __restrict__ W,   // [128][128] row-major (u = y @ W.T)
    const float* __restrict__ b)
{
    __shared__ float W_c[EDIM][HH + 4];    // [32][132] (16B-aligned rows)
    __shared__ float y_s[64][EDIM + 1];    // [64][33]
    const int tid = threadIdx.x;
    const int tr = tid >> 4, tc = tid & 15;
    const int rblock = blockIdx.x * 64;

    float acc[4][8];
    {
        float4 b0 = *(const float4*)(b + tc * 8);
        float4 b1 = *(const float4*)(b + tc * 8 + 4);
#pragma unroll
        for (int i = 0; i < 4; i++) {
            acc[i][0] = b0.x; acc[i][1] = b0.y; acc[i][2] = b0.z; acc[i][3] = b0.w;
            acc[i][4] = b1.x; acc[i][5] = b1.y; acc[i][6] = b1.z; acc[i][7] = b1.w;
        }
    }

    for (int kc = 0; kc < 4; kc++) {
        for (int idx = tid; idx < 4096; idx += 256) {
            int c = idx >> 5, kk = idx & 31;
            W_c[kk][c] = W[c * HH + kc * 32 + kk];
        }
        for (int idx = tid; idx < 2048; idx += 256) {
            int r = idx >> 5, kk = idx & 31;
            int row = rblock + r;
            y_s[r][kk] = (row < NN) ? g_y[(size_t)row * HH + kc * 32 + kk] : 0.f;
        }
        __syncthreads();
#pragma unroll
        for (int k = 0; k < 32; k++) {
            float yv[4];
#pragma unroll
            for (int i = 0; i < 4; i++) yv[i] = y_s[tr * 4 + i][k];
            float4 w0 = *(const float4*)&W_c[k][tc * 8];
            float4 w1 = *(const float4*)&W_c[k][tc * 8 + 4];
#pragma unroll
            for (int i = 0; i < 4; i++) {
                acc[i][0] += yv[i] * w0.x; acc[i][1] += yv[i] * w0.y;
                acc[i][2] += yv[i] * w0.z; acc[i][3] += yv[i] * w0.w;
                acc[i][4] += yv[i] * w1.x; acc[i][5] += yv[i] * w1.y;
                acc[i][6] += yv[i] * w1.z; acc[i][7] += yv[i] * w1.w;
            }
        }
        __syncthreads();
    }

#pragma unroll
    for (int i = 0; i < 4; i++) {
        int row = rblock + tr * 4 + i;
        if (row < NN) {
            float4 o0 = make_float4(acc[i][0], acc[i][1], acc[i][2], acc[i][3]);
            float4 o1 = make_float4(acc[i][4], acc[i][5], acc[i][6], acc[i][7]);
            *(float4*)(g_u + (size_t)row * HH + tc * 8) = o0;
            *(float4*)(g_u + (size_t)row * HH + tc * 8 + 4) = o1;
        }
    }
}

// ---------------- per-channel BN stats ----------------
__global__ void colreduce_kernel() {
    const int c = threadIdx.x;   // 128 threads
    const int r0 = blockIdx.x * 256;
    const int r1 = min(r0 + 256, NN);
    float s = 0.f, s2 = 0.f;
    for (int r = r0; r < r1; r++) {
        float v = g_u[(size_t)r * HH + c];
        s += v; s2 += v * v;
    }
    atomicAdd(&g_sum[c], s);
    atomicAdd(&g_sumsq[c], s2);
}

__global__ void stats_kernel(const float* __restrict__ gamma,
                             const float* __restrict__ beta) {
    int c = threadIdx.x;
    float m = g_sum[c] * (1.f / NN);
    float v = g_sumsq[c] * (1.f / NN) - m * m;
    float rs = rsqrtf(v + BN_EPS);
    float sc = rs * gamma[c];
    g_scale[c] = sc;
    g_shift[c] = beta[c] - m * sc;
}

// ---------------- normalize: h = act(u*scale+shift) ----------------
// mode 0: relu, also writes g_y (= next layer's accumulator init) and rezeroes stats
// mode 1: sigmoid(relu(.))
__global__ void normalize_kernel(int mode, int n4) {
    if (mode == 0 && blockIdx.x == 0 && threadIdx.x < HH) {
        g_sum[threadIdx.x] = 0.f;
        g_sumsq[threadIdx.x] = 0.f;
    }
    int i = blockIdx.x * blockDim.x + threadIdx.x;
    if (i >= n4) return;
    int c0 = (i * 4) & 127;
    float4 sc = *(const float4*)(g_scale + c0);
    float4 sh = *(const float4*)(g_shift + c0);
    float4 v = ((const float4*)g_u)[i];
    v.x = fmaxf(v.x * sc.x + sh.x, 0.f);
    v.y = fmaxf(v.y * sc.y + sh.y, 0.f);
    v.z = fmaxf(v.z * sc.z + sh.z, 0.f);
    v.w = fmaxf(v.w * sc.w + sh.w, 0.f);
    if (mode == 1) {
        v.x = 1.f / (1.f + expf(-v.x));
        v.y = 1.f / (1.f + expf(-v.y));
        v.z = 1.f / (1.f + expf(-v.z));
        v.w = 1.f / (1.f + expf(-v.w));
    }
    ((float4*)g_h)[i] = v;
    if (mode == 0) ((float4*)g_y)[i] = v;   // layer2 accumulator init
}

// ---------------- per-graph mean pooling (batch is sorted) ----------------
__device__ __forceinline__ int lb_search(const void* bp, int target, bool i64) {
    int l = 0, r = NN;
    while (l < r) {
        int m = (l + r) >> 1;
        if (read_idx(bp, m, i64) < (long long)target) l = m + 1; else r = m;
    }
    return l;
}

__global__ void pool_kernel(const void* __restrict__ batchv) {
    const int g = blockIdx.x, c = threadIdx.x;  // 64 blocks x 128 threads
    const bool i64 = (g_idx64 != 0);
    int lo = lb_search(batchv, g, i64);
    int hi = lb_search(batchv, g + 1, i64);
    float s = 0.f;
    for (int i = lo; i < hi; i++) s += g_h[(size_t)i * HH + c];
    int cnt = hi - lo;
    g_pooled[g * HH + c] = s / fmaxf((float)cnt, 1.f);
}

// ---------------- fused action MLP (1 block, 128 threads; thread c owns column c) ----------------
__device__ __forceinline__ void mlp_layer(float* z, const float* p_s,
                                          const float* __restrict__ Wrow,
                                          float bias, float gamma, float beta) {
#pragma unroll
    for (int r = 0; r < GG; r++) z[r] = bias;
    for (int k = 0; k < HH; k += 4) {
        float4 w = *(const float4*)(Wrow + k);
#pragma unroll
        for (int r = 0; r < GG; r++) {
            float4 p = *(const float4*)(p_s + r * HH + k);
            z[r] += w.x * p.x + w.y * p.y + w.z * p.z + w.w * p.w;
        }
    }
    float m = 0.f, s2 = 0.f;
#pragma unroll
    for (int r = 0; r < GG; r++) { m += z[r]; s2 += z[r] * z[r]; }
    m *= (1.f / GG);
    float v = s2 * (1.f / GG) - m * m;
    float sc = rsqrtf(v + BN_EPS) * gamma;
    float sh = beta - m * sc;
#pragma unroll
    for (int r = 0; r < GG; r++) z[r] = fmaxf(z[r] * sc + sh, 0.f);
}

__global__ void __launch_bounds__(128) mlp_kernel(
    const float* __restrict__ A1w, const float* __restrict__ A1b,
    const float* __restrict__ Ag1, const float* __restrict__ Ab1,
    const float* __restrict__ A2w, const float* __restrict__ A2b,
    const float* __restrict__ Ag2, const float* __restrict__ Ab2,
    const float* __restrict__ A3w, const float* __restrict__ A3b,
    float* __restrict__ out)
{
    __shared__ float p_s[GG * HH];
    const int c = threadIdx.x;
    for (int idx = c; idx < GG * HH; idx += 128) p_s[idx] = g_pooled[idx];
    __syncthreads();

    float z[GG];
    mlp_layer(z, p_s, A1w + c * HH, A1b[c], Ag1[c], Ab1[c]);
    __syncthreads();
#pragma unroll
    for (int r = 0; r < GG; r++) p_s[r * HH + c] = z[r];
    __syncthreads();

    mlp_layer(z, p_s, A2w + c * HH, A2b[c], Ag2[c], Ab2[c]);
    __syncthreads();
#pragma unroll
    for (int r = 0; r < GG; r++) p_s[r * HH + c] = z[r];
    __syncthreads();

    for (int idx = c; idx < GG * AA; idx += 128) {
        int r = idx >> 4, a2 = idx & 15;
        float acc = A3b[a2];
        for (int k = 0; k < HH; k++) acc += p_s[r * HH + k] * A3w[a2 * HH + k];
        out[idx] = 1.f / (1.f + expf(-acc));
    }
}

// ---------------- host launch ----------------
extern "C" void kernel_launch(void* const* d_in, const int* in_sizes, int n_in,
                              void* d_out, int out_size) {
    // Determine input ordering: setup_inputs-dict order vs reference-signature order.
    // setup order: d_in[2] = edge_index (2*E elements); signature order: d_in[2] = W1 (16384).
    int ix, iea, iei, ib;
    int iW1, ib1, iWe1, ibe1, ig1, ibt1, iW2, ib2, iWe2, ibe2, ig2, ibt2;
    int iA1w, iA1b, iAg1, iAb1, iA2w, iA2b, iAg2, iAb2, iA3w, iA3b;
    if (in_sizes[2] == 2 * EE || in_sizes[2] == 4 * EE) {
        // setup_inputs order
        ix = 0; iea = 1; iei = 2; ib = 3;
        iW1 = 4; ib1 = 5; iWe1 = 6; ibe1 = 7; ig1 = 8; ibt1 = 9;
        iW2 = 10; ib2 = 11; iWe2 = 12; ibe2 = 13; ig2 = 14; ibt2 = 15;
        iA1w = 16; iA1b = 17; iAg1 = 18; iAb1 = 19;
        iA2w = 20; iA2b = 21; iAg2 = 22; iAb2 = 23; iA3w = 24; iA3b = 25;
    } else {
        // reference-signature order
        ix = 0; iea = 1;
        iW1 = 2; ib1 = 3; iWe1 = 4; ibe1 = 5; ig1 = 6; ibt1 = 7;
        iW2 = 8; ib2 = 9; iWe2 = 10; ibe2 = 11; ig2 = 12; ibt2 = 13;
        iA1w = 14; iA1b = 15; iAg1 = 16; iAb1 = 17;
        iA2w = 18; iA2b = 19; iAg2 = 20; iAb2 = 21; iA3w = 22; iA3b = 23;
        iei = 24; ib = 25;
    }

    const float* x   = (const float*)d_in[ix];
    const float* ea  = (const float*)d_in[iea];
    const void*  ei  = d_in[iei];
    const void*  bat = d_in[ib];
    float* out = (float*)d_out;

    const int n4 = NN * HH / 4;            // 1,600,000
    const int copy_blocks = (n4 + 255) / 256;
    const int edge_blocks = EE / 64;       // 12,500 (8 warps x 8 edges)
    const int gemm_blocks = (NN + 63) / 64;
    const int red_blocks  = (NN + 255) / 256;

    detect_kernel<<<1, 256>>>((const unsigned int*)ei);

    // ---- layer 1 ----
    copy_init_kernel<<<copy_blocks, 256>>>((const float4*)x, n4);
    edge_kernel<<<edge_blocks, 256>>>(x, 0, ea, ei,
                                      (const float*)d_in[iWe1], (const float*)d_in[ibe1]);
    node_gemm_kernel<<<gemm_blocks, 256>>>((const float*)d_in[iW1], (const float*)d_in[ib1]);
    colreduce_kernel<<<red_blocks, 128>>>();
    stats_kernel<<<1, 128>>>((const float*)d_in[ig1], (const float*)d_in[ibt1]);
    normalize_kernel<<<copy_blocks, 256>>>(0, n4);   // relu; also seeds g_y = h, rezeroes stats

    // ---- layer 2 ----
    edge_kernel<<<edge_blocks, 256>>>(x, 1, ea, ei,
                                      (const float*)d_in[iWe2], (const float*)d_in[ibe2]);
    node_gemm_kernel<<<gemm_blocks, 256>>>((const float*)d_in[iW2], (const float*)d_in[ib2]);
    colreduce_kernel<<<red_blocks, 128>>>();
    stats_kernel<<<1, 128>>>((const float*)d_in[ig2], (const float*)d_in[ibt2]);
    normalize_kernel<<<copy_blocks, 256>>>(1, n4);   // sigmoid(relu(.))

    // ---- pool + MLP ----
    pool_kernel<<<GG, 128>>>(bat);
    mlp_kernel<<<1, 128>>>((const float*)d_in[iA1w], (const float*)d_in[iA1b],
                           (const float*)d_in[iAg1], (const float*)d_in[iAb1],
                           (const float*)d_in[iA2w], (const float*)d_in[iA2b],
                           (const float*)d_in[iAg2], (const float*)d_in[iAb2],
                           (const float*)d_in[iA3w], (const float*)d_in[iA3b], out);
}

// round 2
// speedup vs baseline: 1.5512x; 1.5512x over previous
#include <cuda_runtime.h>
#include <math.h>

#define NN 50000
#define EE 800000
#define HH 128
#define EDIM 32
#define GG 64
#define AA 16
#define BN_EPS 1e-5f

// ---------------- scratch (static device globals; no allocation) ----------------
__device__ float g_y[(size_t)NN * HH];   // x + agg (GEMM input)
__device__ float g_u[(size_t)NN * HH];   // GEMM output (pre-BN)
__device__ float g_h[(size_t)NN * HH];   // layer output
__device__ float g_sum[HH];
__device__ float g_sumsq[HH];
__device__ float g_scale[HH];
__device__ float g_shift[HH];
__device__ float g_pooled[GG * HH];
__device__ int   g_idx64;                // 1 if edge_index/batch are int64

// ---------------- int32/int64 index handling ----------------
__device__ __forceinline__ long long read_idx(const void* p, long long i, bool i64) {
    if (i64) return ((const long long*)p)[i];
    return (long long)((const int*)p)[i];
}

__global__ void detect_kernel(const unsigned int* __restrict__ w) {
    __shared__ int f;
    if (threadIdx.x == 0) f = 0;
    __syncthreads();
    int local = 0;
    for (int i = threadIdx.x * 2 + 1; i < 8192; i += 512)
        if (w[i]) local = 1;
    if (local) atomicOr(&f, 1);
    __syncthreads();
    if (threadIdx.x == 0) g_idx64 = f ? 0 : 1;
}

// ---------------- tf32 helpers ----------------
__device__ __forceinline__ unsigned tf32_of(float f) {
    unsigned u;
    asm("cvt.rna.tf32.f32 %0, %1;" : "=r"(u) : "f"(f));
    return u;
}
__device__ __forceinline__ void split_tf32(float f, unsigned& hi, unsigned& lo) {
    hi = tf32_of(f);
    lo = tf32_of(f - __uint_as_float(hi));
}
__device__ __forceinline__ void mma_tf32(float& c0, float& c1, float& c2, float& c3,
                                         unsigned a0, unsigned a1, unsigned a2, unsigned a3,
                                         unsigned b0, unsigned b1) {
    asm volatile("mma.sync.aligned.m16n8k8.row.col.f32.tf32.tf32.f32 "
                 "{%0,%1,%2,%3}, {%4,%5,%6,%7}, {%8,%9}, {%0,%1,%2,%3};"
                 : "+f"(c0), "+f"(c1), "+f"(c2), "+f"(c3)
                 : "r"(a0), "r"(a1), "r"(a2), "r"(a3), "r"(b0), "r"(b1));
}

// ---------------- y = src (copy), zero BN stats ----------------
__global__ void copy_init_kernel(const float4* __restrict__ src, int n4) {
    if (blockIdx.x == 0 && threadIdx.x < HH) {
        g_sum[threadIdx.x] = 0.f;
        g_sumsq[threadIdx.x] = 0.f;
    }
    int i = blockIdx.x * blockDim.x + threadIdx.x;
    if (i < n4) ((float4*)g_y)[i] = src[i];
}

// ---------------- edge kernel (tensor-core elin, 3xTF32) ----------------
// Per warp-tile: 16 edges. elin[16][128] = ea[16][32] @ We.T via m16n8k8 tf32.
// k-axis permuted so A fragments come from coalesced float4 loads.
// Epilogue: pair shfl to form float4, gather x[src], relu, red.v4 into g_y[dst].
#define NTILES 50000         // EE/16
#define WTILES 8             // 16-edge tiles per warp
__global__ void __launch_bounds__(256) edge_mma_kernel(
    const float* __restrict__ xin_ext, int use_h,
    const float* __restrict__ ea,
    const void* __restrict__ eiv,
    const float* __restrict__ We,   // [128][32] row-major
    const float* __restrict__ be)
{
    __shared__ float4 bfrag[16 * 4 * 32];   // [nt][kk][lane] = (bhi0,bhi1,blo0,blo1)  32KB
    __shared__ float be_s[HH];

    const int tid = threadIdx.x;
    // Stage pre-split B fragments (shared by all warps)
    for (int idx = tid; idx < 2048; idx += 256) {
        int nt = idx >> 7, kk = (idx >> 5) & 3, ln = idx & 31;
        int g2 = ln >> 2, t2 = ln & 3;
        int c = nt * 8 + g2;
        float w0 = We[c * EDIM + 8 * t2 + kk];
        float w1 = We[c * EDIM + 8 * t2 + 4 + kk];
        unsigned h0, l0, h1, l1;
        split_tf32(w0, h0, l0);
        split_tf32(w1, h1, l1);
        bfrag[idx] = make_float4(__uint_as_float(h0), __uint_as_float(h1),
                                 __uint_as_float(l0), __uint_as_float(l1));
    }
    if (tid < HH) be_s[tid] = be[tid];
    __syncthreads();

    const float* __restrict__ xin = use_h ? g_h : xin_ext;
    const int lane = tid & 31, warp = tid >> 5;
    const int g = lane >> 2, t = lane & 3;
    const bool i64 = (g_idx64 != 0);
    const bool even = ((t & 1) == 0);
    const int erow = even ? g : g + 8;          // which edge this thread's output rows map to
    const int cboff = 2 * (t & ~1);             // 0,0,4,4 for t=0..3

    for (int it = 0; it < WTILES; it++) {
        int tile = (blockIdx.x * 8 + warp) * WTILES + it;
        if (tile >= NTILES) break;
        long long e0 = (long long)tile * 16;

        int sv = 0, dv = 0;
        if (lane < 16) {
            sv = (int)read_idx(eiv, e0 + lane, i64);
            dv = (int)read_idx(eiv, (long long)EE + e0 + lane, i64);
        }
        int my_s = __shfl_sync(0xffffffffu, sv, erow);
        int my_d = __shfl_sync(0xffffffffu, dv, erow);
        const float* srcp = xin + (size_t)my_s * HH + cboff;
        float*       dstp = g_y + (size_t)my_d * HH + cboff;

        // A: rows e0+g and e0+g+8, floats [8t .. 8t+7]
        const float* ar0 = ea + (size_t)(e0 + g) * EDIM + 8 * t;
        const float* ar1 = ea + (size_t)(e0 + g + 8) * EDIM + 8 * t;
        float4 u0 = *(const float4*)ar0;
        float4 u1 = *(const float4*)(ar0 + 4);
        float4 v0 = *(const float4*)ar1;
        float4 v1 = *(const float4*)(ar1 + 4);
        float ua0[4] = {u0.x, u0.y, u0.z, u0.w};
        float ua1[4] = {u1.x, u1.y, u1.z, u1.w};
        float va0[4] = {v0.x, v0.y, v0.z, v0.w};
        float va1[4] = {v1.x, v1.y, v1.z, v1.w};

        unsigned ahi[4][4], alo[4][4];
#pragma unroll
        for (int kk = 0; kk < 4; kk++) {
            split_tf32(ua0[kk], ahi[kk][0], alo[kk][0]);
            split_tf32(va0[kk], ahi[kk][1], alo[kk][1]);
            split_tf32(ua1[kk], ahi[kk][2], alo[kk][2]);
            split_tf32(va1[kk], ahi[kk][3], alo[kk][3]);
        }

#pragma unroll 2
        for (int nt = 0; nt < 16; nt++) {
            float2 b2 = *(const float2*)(be_s + nt * 8 + 2 * t);
            float c0 = b2.x, c1 = b2.y, c2 = b2.x, c3 = b2.y;
#pragma unroll
            for (int kk = 0; kk < 4; kk++) {
                float4 bf = bfrag[(nt * 4 + kk) * 32 + lane];
                unsigned bh0 = __float_as_uint(bf.x), bh1 = __float_as_uint(bf.y);
                unsigned bl0 = __float_as_uint(bf.z), bl1 = __float_as_uint(bf.w);
                mma_tf32(c0, c1, c2, c3, ahi[kk][0], ahi[kk][1], ahi[kk][2], ahi[kk][3], bh0, bh1);
                mma_tf32(c0, c1, c2, c3, alo[kk][0], alo[kk][1], alo[kk][2], alo[kk][3], bh0, bh1);
                mma_tf32(c0, c1, c2, c3, ahi[kk][0], ahi[kk][1], ahi[kk][2], ahi[kk][3], bl0, bl1);
            }
            // pair exchange: build one float4 per thread
            float s0 = even ? c2 : c0;
            float s1 = even ? c3 : c1;
            float r0 = __shfl_xor_sync(0xffffffffu, s0, 1);
            float r1 = __shfl_xor_sync(0xffffffffu, s1, 1);
            float o0, o1, o2, o3;
            if (even) { o0 = c0; o1 = c1; o2 = r0; o3 = r1; }
            else      { o0 = r0; o1 = r1; o2 = c2; o3 = c3; }

            float4 xv = *(const float4*)(srcp + nt * 8);
            o0 = fmaxf(o0 + xv.x, 0.f);
            o1 = fmaxf(o1 + xv.y, 0.f);
            o2 = fmaxf(o2 + xv.z, 0.f);
            o3 = fmaxf(o3 + xv.w, 0.f);
            asm volatile("red.global.add.v4.f32 [%0], {%1,%2,%3,%4};"
                         :: "l"(dstp + nt * 8), "f"(o0), "f"(o1), "f"(o2), "f"(o3) : "memory");
        }
    }
}

// ---------------- node GEMM via tensor cores: u = g_y @ W.T + b ----------------
// Block: 256 threads (8 warps), 128 rows. Warp: 16 rows x 128 cols, K looped in 4 blocks of 32.
__global__ void __launch_bounds__(256) node_gemm_mma_kernel(
    const float* __restrict__ W,   // [128][128] row-major
    const float* __restrict__ b)
{
    __shared__ float4 bfrag[16 * 4 * 32];   // re-staged per k-block  32KB
    __shared__ float b_s[HH];

    const int tid = threadIdx.x;
    const int lane = tid & 31, warp = tid >> 5;
    const int g = lane >> 2, t = lane & 3;
    const int rowbase = blockIdx.x * 128 + warp * 16;
    const bool active = (rowbase < NN);      // NN % 16 == 0, so all-or-nothing per warp tile
    const bool even = ((t & 1) == 0);
    const int cboff = 2 * (t & ~1);

    if (tid < HH) b_s[tid] = b[tid];

    float C[16][4];
#pragma unroll
    for (int nt = 0; nt < 16; nt++)
#pragma unroll
        for (int j = 0; j < 4; j++) C[nt][j] = 0.f;

    for (int kb = 0; kb < 4; kb++) {
        __syncthreads();
        for (int idx = tid; idx < 2048; idx += 256) {
            int nt = idx >> 7, kk = (idx >> 5) & 3, ln = idx & 31;
            int g2 = ln >> 2, t2 = ln & 3;
            int c = nt * 8 + g2;
            int k0 = kb * 32 + 8 * t2 + kk;
            float w0 = W[c * HH + k0];
            float w1 = W[c * HH + k0 + 4];
            unsigned h0, l0, h1, l1;
            split_tf32(w0, h0, l0);
            split_tf32(w1, h1, l1);
            bfrag[idx] = make_float4(__uint_as_float(h0), __uint_as_float(h1),
                                     __uint_as_float(l0), __uint_as_float(l1));
        }
        __syncthreads();

        if (active) {
            const float* ar0 = g_y + (size_t)(rowbase + g) * HH + kb * 32 + 8 * t;
            const float* ar1 = g_y + (size_t)(rowbase + g + 8) * HH + kb * 32 + 8 * t;
            float4 u0 = *(const float4*)ar0;
            float4 u1 = *(const float4*)(ar0 + 4);
            float4 v0 = *(const float4*)ar1;
            float4 v1 = *(const float4*)(ar1 + 4);
            float ua0[4] = {u0.x, u0.y, u0.z, u0.w};
            float ua1[4] = {u1.x, u1.y, u1.z, u1.w};
            float va0[4] = {v0.x, v0.y, v0.z, v0.w};
            float va1[4] = {v1.x, v1.y, v1.z, v1.w};

            unsigned ahi[4][4], alo[4][4];
#pragma unroll
            for (int kk = 0; kk < 4; kk++) {
                split_tf32(ua0[kk], ahi[kk][0], alo[kk][0]);
                split_tf32(va0[kk], ahi[kk][1], alo[kk][1]);
                split_tf32(ua1[kk], ahi[kk][2], alo[kk][2]);
                split_tf32(va1[kk], ahi[kk][3], alo[kk][3]);
            }
#pragma unroll
            for (int nt = 0; nt < 16; nt++) {
#pragma unroll
                for (int kk = 0; kk < 4; kk++) {
                    float4 bf = bfrag[(nt * 4 + kk) * 32 + lane];
                    unsigned bh0 = __float_as_uint(bf.x), bh1 = __float_as_uint(bf.y);
                    unsigned bl0 = __float_as_uint(bf.z), bl1 = __float_as_uint(bf.w);
                    mma_tf32(C[nt][0], C[nt][1], C[nt][2], C[nt][3],
                             ahi[kk][0], ahi[kk][1], ahi[kk][2], ahi[kk][3], bh0, bh1);
                    mma_tf32(C[nt][0], C[nt][1], C[nt][2], C[nt][3],
                             alo[kk][0], alo[kk][1], alo[kk][2], alo[kk][3], bh0, bh1);
                    mma_tf32(C[nt][0], C[nt][1], C[nt][2], C[nt][3],
                             ahi[kk][0], ahi[kk][1], ahi[kk][2], ahi[kk][3], bl0, bl1);
                }
            }
        }
    }

    if (active) {
        const int orow = rowbase + (even ? g : g + 8);
        float* outp = g_u + (size_t)orow * HH + cboff;
#pragma unroll
        for (int nt = 0; nt < 16; nt++) {
            float c0 = C[nt][0] + b_s[nt * 8 + 2 * t];
            float c1 = C[nt][1] + b_s[nt * 8 + 2 * t + 1];
            float c2 = C[nt][2] + b_s[nt * 8 + 2 * t];
            float c3 = C[nt][3] + b_s[nt * 8 + 2 * t + 1];
            float s0 = even ? c2 : c0;
            float s1 = even ? c3 : c1;
            float r0 = __shfl_xor_sync(0xffffffffu, s0, 1);
            float r1 = __shfl_xor_sync(0xffffffffu, s1, 1);
            float4 o;
            if (even) { o = make_float4(c0, c1, r0, r1); }
            else      { o = make_float4(r0, r1, c2, c3); }
            *(float4*)(outp + nt * 8) = o;
        }
    }
}

// ---------------- per-channel BN stats ----------------
__global__ void colreduce_kernel() {
    const int c = threadIdx.x;   // 128 threads, coalesced over rows
    const int r0 = blockIdx.x * 256;
    const int r1 = min(r0 + 256, NN);
    float s = 0.f, s2 = 0.f;
    for (int r = r0; r < r1; r++) {
        float v = g_u[(size_t)r * HH + c];
        s += v; s2 += v * v;
    }
    atomicAdd(&g_sum[c], s);
    atomicAdd(&g_sumsq[c], s2);
}

__global__ void stats_kernel(const float* __restrict__ gamma,
                             const float* __restrict__ beta) {
    int c = threadIdx.x;
    float m = g_sum[c] * (1.f / NN);
    float v = g_sumsq[c] * (1.f / NN) - m * m;
    float rs = rsqrtf(v + BN_EPS);
    float sc = rs * gamma[c];
    g_scale[c] = sc;
    g_shift[c] = beta[c] - m * sc;
}

// ---------------- normalize: h = act(u*scale+shift) ----------------
__global__ void normalize_kernel(int mode, int n4) {
    if (mode == 0 && blockIdx.x == 0 && threadIdx.x < HH) {
        g_sum[threadIdx.x] = 0.f;
        g_sumsq[threadIdx.x] = 0.f;
    }
    int i = blockIdx.x * blockDim.x + threadIdx.x;
    if (i >= n4) return;
    int c0 = (i * 4) & 127;
    float4 sc = *(const float4*)(g_scale + c0);
    float4 sh = *(const float4*)(g_shift + c0);
    float4 v = ((const float4*)g_u)[i];
    v.x = fmaxf(v.x * sc.x + sh.x, 0.f);
    v.y = fmaxf(v.y * sc.y + sh.y, 0.f);
    v.z = fmaxf(v.z * sc.z + sh.z, 0.f);
    v.w = fmaxf(v.w * sc.w + sh.w, 0.f);
    if (mode == 1) {
        v.x = 1.f / (1.f + expf(-v.x));
        v.y = 1.f / (1.f + expf(-v.y));
        v.z = 1.f / (1.f + expf(-v.z));
        v.w = 1.f / (1.f + expf(-v.w));
    }
    ((float4*)g_h)[i] = v;
    if (mode == 0) ((float4*)g_y)[i] = v;
}

// ---------------- per-graph mean pooling ----------------
__device__ __forceinline__ int lb_search(const void* bp, int target, bool i64) {
    int l = 0, r = NN;
    while (l < r) {
        int m = (l + r) >> 1;
        if (read_idx(bp, m, i64) < (long long)target) l = m + 1; else r = m;
    }
    return l;
}

__global__ void pool_kernel(const void* __restrict__ batchv) {
    const int g = blockIdx.x, c = threadIdx.x;
    const bool i64 = (g_idx64 != 0);
    int lo = lb_search(batchv, g, i64);
    int hi = lb_search(batchv, g + 1, i64);
    float s = 0.f;
    for (int i = lo; i < hi; i++) s += g_h[(size_t)i * HH + c];
    int cnt = hi - lo;
    g_pooled[g * HH + c] = s / fmaxf((float)cnt, 1.f);
}

// ---------------- fused action MLP ----------------
__device__ __forceinline__ void mlp_layer(float* z, const float* p_s,
                                          const float* __restrict__ Wrow,
                                          float bias, float gamma, float beta) {
#pragma unroll
    for (int r = 0; r < GG; r++) z[r] = bias;
    for (int k = 0; k < HH; k += 4) {
        float4 w = *(const float4*)(Wrow + k);
#pragma unroll
        for (int r = 0; r < GG; r++) {
            float4 p = *(const float4*)(p_s + r * HH + k);
            z[r] += w.x * p.x + w.y * p.y + w.z * p.z + w.w * p.w;
        }
    }
    float m = 0.f, s2 = 0.f;
#pragma unroll
    for (int r = 0; r < GG; r++) { m += z[r]; s2 += z[r] * z[r]; }
    m *= (1.f / GG);
    float v = s2 * (1.f / GG) - m * m;
    float sc = rsqrtf(v + BN_EPS) * gamma;
    float sh = beta - m * sc;
#pragma unroll
    for (int r = 0; r < GG; r++) z[r] = fmaxf(z[r] * sc + sh, 0.f);
}

__global__ void __launch_bounds__(128) mlp_kernel(
    const float* __restrict__ A1w, const float* __restrict__ A1b,
    const float* __restrict__ Ag1, const float* __restrict__ Ab1,
    const float* __restrict__ A2w, const float* __restrict__ A2b,
    const float* __restrict__ Ag2, const float* __restrict__ Ab2,
    const float* __restrict__ A3w, const float* __restrict__ A3b,
    float* __restrict__ out)
{
    __shared__ float p_s[GG * HH];
    const int c = threadIdx.x;
    for (int idx = c; idx < GG * HH; idx += 128) p_s[idx] = g_pooled[idx];
    __syncthreads();

    float z[GG];
    mlp_layer(z, p_s, A1w + c * HH, A1b[c], Ag1[c], Ab1[c]);
    __syncthreads();
#pragma unroll
    for (int r = 0; r < GG; r++) p_s[r * HH + c] = z[r];
    __syncthreads();

    mlp_layer(z, p_s, A2w + c * HH, A2b[c], Ag2[c], Ab2[c]);
    __syncthreads();
#pragma unroll
    for (int r = 0; r < GG; r++) p_s[r * HH + c] = z[r];
    __syncthreads();

    for (int idx = c; idx < GG * AA; idx += 128) {
        int r = idx >> 4, a2 = idx & 15;
        float acc = A3b[a2];
        for (int k = 0; k < HH; k++) acc += p_s[r * HH + k] * A3w[a2 * HH + k];
        out[idx] = 1.f / (1.f + expf(-acc));
    }
}

// ---------------- host launch ----------------
extern "C" void kernel_launch(void* const* d_in, const int* in_sizes, int n_in,
                              void* d_out, int out_size) {
    int ix, iea, iei, ib;
    int iW1, ib1, iWe1, ibe1, ig1, ibt1, iW2, ib2, iWe2, ibe2, ig2, ibt2;
    int iA1w, iA1b, iAg1, iAb1, iA2w, iA2b, iAg2, iAb2, iA3w, iA3b;
    if (in_sizes[2] == 2 * EE || in_sizes[2] == 4 * EE) {
        ix = 0; iea = 1; iei = 2; ib = 3;
        iW1 = 4; ib1 = 5; iWe1 = 6; ibe1 = 7; ig1 = 8; ibt1 = 9;
        iW2 = 10; ib2 = 11; iWe2 = 12; ibe2 = 13; ig2 = 14; ibt2 = 15;
        iA1w = 16; iA1b = 17; iAg1 = 18; iAb1 = 19;
        iA2w = 20; iA2b = 21; iAg2 = 22; iAb2 = 23; iA3w = 24; iA3b = 25;
    } else {
        ix = 0; iea = 1;
        iW1 = 2; ib1 = 3; iWe1 = 4; ibe1 = 5; ig1 = 6; ibt1 = 7;
        iW2 = 8; ib2 = 9; iWe2 = 10; ibe2 = 11; ig2 = 12; ibt2 = 13;
        iA1w = 14; iA1b = 15; iAg1 = 16; iAb1 = 17;
        iA2w = 18; iA2b = 19; iAg2 = 20; iAb2 = 21; iA3w = 22; iA3b = 23;
        iei = 24; ib = 25;
    }

    const float* x   = (const float*)d_in[ix];
    const float* ea  = (const float*)d_in[iea];
    const void*  ei  = d_in[iei];
    const void*  bat = d_in[ib];
    float* out = (float*)d_out;

    const int n4 = NN * HH / 4;
    const int copy_blocks = (n4 + 255) / 256;
    const int edge_blocks = (NTILES + 63) / 64;      // 782 (8 warps x 8 tiles x 16 edges)
    const int gemm_blocks = (NN + 127) / 128;        // 391
    const int red_blocks  = (NN + 255) / 256;

    detect_kernel<<<1, 256>>>((const unsigned int*)ei);

    // ---- layer 1 ----
    copy_init_kernel<<<copy_blocks, 256>>>((const float4*)x, n4);
    edge_mma_kernel<<<edge_blocks, 256>>>(x, 0, ea, ei,
                                          (const float*)d_in[iWe1], (const float*)d_in[ibe1]);
    node_gemm_mma_kernel<<<gemm_blocks, 256>>>((const float*)d_in[iW1], (const float*)d_in[ib1]);
    colreduce_kernel<<<red_blocks, 128>>>();
    stats_kernel<<<1, 128>>>((const float*)d_in[ig1], (const float*)d_in[ibt1]);
    normalize_kernel<<<copy_blocks, 256>>>(0, n4);

    // ---- layer 2 ----
    edge_mma_kernel<<<edge_blocks, 256>>>(x, 1, ea, ei,
                                          (const float*)d_in[iWe2], (const float*)d_in[ibe2]);
    node_gemm_mma_kernel<<<gemm_blocks, 256>>>((const float*)d_in[iW2], (const float*)d_in[ib2]);
    colreduce_kernel<<<red_blocks, 128>>>();
    stats_kernel<<<1, 128>>>((const float*)d_in[ig2], (const float*)d_in[ibt2]);
    normalize_kernel<<<copy_blocks, 256>>>(1, n4);

    // ---- pool + MLP ----
    pool_kernel<<<GG, 128>>>(bat);
    mlp_kernel<<<1, 128>>>((const float*)d_in[iA1w], (const float*)d_in[iA1b],
                           (const float*)d_in[iAg1], (const float*)d_in[iAb1],
                           (const float*)d_in[iA2w], (const float*)d_in[iA2b],
                           (const float*)d_in[iAg2], (const float*)d_in[iAb2],
                           (const float*)d_in[iA3w], (const float*)d_in[iA3b], out);
}